// round 14
// baseline (speedup 1.0000x reference)
#include <cuda_runtime.h>
#include <cuda_bf16.h>
#include <math.h>
#include <stdint.h>

// Problem constants (dataset-fixed: z[16,128,32,32], e[8192,128], log_sigma[1])
#define NTOK  16384
#define MCODE 8192
#define CDIM  128
#define BDIM  16
#define HWDIM 1024
#define PTILES (NTOK / 128)     /* 128 CTAs, 128 rows each */
#define QTILES (MCODE / 128)    /* 64 streamed q tiles */

// ---------------- device scratch ----------------
__device__ __nv_bfloat16 g_zhi[(size_t)NTOK * CDIM];
__device__ __nv_bfloat16 g_ehi[(size_t)MCODE * CDIM];
__device__ float g_zsq[NTOK], g_esq[MCODE];
__device__ float g_rm[NTOK],  g_rs[NTOK];
__device__ float g_cpm[(size_t)PTILES * MCODE];
__device__ float g_cps[(size_t)PTILES * MCODE];
__device__ float g_cm[MCODE], g_cs[MCODE];

// ---------------- helpers ----------------
__device__ __forceinline__ uint32_t smem_u32(const void* p) {
    uint32_t a;
    asm("{ .reg .u64 t; cvta.to.shared.u64 t, %1; cvt.u32.u64 %0, t; }" : "=r"(a) : "l"(p));
    return a;
}
__device__ __forceinline__ float ex2f(float x) {
    float r; asm("ex2.approx.ftz.f32 %0, %1;" : "=f"(r) : "f"(x)); return r;
}
__device__ __forceinline__ void merge_ms(float& m, float& s, float m2, float s2) {
    float e = ex2f(-fabsf(m - m2));
    if (m >= m2) { s = s + s2 * e; }
    else         { s = s2 + s * e; m = m2; }
}
__device__ __forceinline__ void cpasync16(uint32_t dst, const void* src) {
    asm volatile("cp.async.cg.shared.global [%0], [%1], 16;" :: "r"(dst), "l"(src) : "memory");
}
__device__ __forceinline__ void cpcommit() {
    asm volatile("cp.async.commit_group;" ::: "memory");
}
template <int N> __device__ __forceinline__ void cpwait() {
    asm volatile("cp.async.wait_group %0;" :: "n"(N) : "memory");
}
__device__ __forceinline__ void ldsm_x4(uint32_t* r, uint32_t addr) {
    asm volatile("ldmatrix.sync.aligned.m8n8.x4.shared.b16 {%0,%1,%2,%3}, [%4];"
                 : "=r"(r[0]), "=r"(r[1]), "=r"(r[2]), "=r"(r[3]) : "r"(addr));
}
__device__ __forceinline__ void mma16816(float* d, const uint32_t* a, const uint32_t* b) {
    asm volatile(
        "mma.sync.aligned.m16n8k16.row.col.f32.bf16.bf16.f32 "
        "{%0,%1,%2,%3}, {%4,%5,%6,%7}, {%8,%9}, {%0,%1,%2,%3};"
        : "+f"(d[0]), "+f"(d[1]), "+f"(d[2]), "+f"(d[3])
        : "r"(a[0]), "r"(a[1]), "r"(a[2]), "r"(a[3]), "r"(b[0]), "r"(b[1]));
}
__device__ __forceinline__ uint32_t packbf2(float a, float b) {
    __nv_bfloat162 t = __floats2bfloat162_rn(a, b);
    return *reinterpret_cast<uint32_t*>(&t);
}

// ---------------- smem layout ----------------
#define OFF_X      0                      /* 128*256 = 32KB             */
#define OFF_Y(b)   (32768 + (b) * 32768)  /* two 32KB Y buffers         */
#define OFF_YSQ    98304                  /* 4 slots x 128 floats = 2KB */
#define OFF_COL    100352                 /* 2*128*2 floats = 2KB       */
#define OFF_REDM   102400                 /* 4*128 floats = 2KB         */
#define OFF_REDS   104448                 /* 4*128 floats = 2KB         */
#define SMEM_BYTES (106496 + 1024)

__device__ __forceinline__ uint32_t swzc(int c, int r) {
    return (uint32_t)(((c >> 3) << 7) + ((((c & 7) ^ (r & 7))) << 4));
}

// ---------------- fused prep: one launch for z + e ----------------
__global__ void fuse_prep(const float* __restrict__ z, const float* __restrict__ e,
                          __nv_bfloat16* __restrict__ zhi, float* __restrict__ zsq,
                          __nv_bfloat16* __restrict__ ehi, float* __restrict__ esq) {
    __shared__ float tile[32 * 129];
    const int t = threadIdx.x;
    if (blockIdx.x < 512) {
        const int b    = blockIdx.x >> 5;
        const int hw0  = (blockIdx.x & 31) * 32;
        const int lane = t & 31;
#pragma unroll
        for (int it = 0; it < 16; ++it) {
            int c = (t >> 5) + it * 8;
            tile[lane * 129 + c] = z[(size_t)b * (CDIM * HWDIM) + (size_t)c * HWDIM + hw0 + lane];
        }
        __syncthreads();
        const int tloc = t >> 3;
        const int c0   = (t & 7) * 16;
        const int n    = b * HWDIM + hw0 + tloc;
        float sq = 0.0f;
        uint32_t hp[8];
#pragma unroll
        for (int i = 0; i < 8; ++i) {
            float a = tile[tloc * 129 + c0 + 2 * i];
            float c = tile[tloc * 129 + c0 + 2 * i + 1];
            sq += a * a + c * c;
            hp[i] = packbf2(a, c);
        }
        uint4* dh = reinterpret_cast<uint4*>(zhi + (size_t)n * CDIM + c0);
        dh[0] = make_uint4(hp[0], hp[1], hp[2], hp[3]);
        dh[1] = make_uint4(hp[4], hp[5], hp[6], hp[7]);
#pragma unroll
        for (int off = 1; off <= 4; off <<= 1) sq += __shfl_xor_sync(0xffffffffu, sq, off);
        if ((t & 7) == 0) zsq[n] = sq;
    } else {
        const int w    = ((blockIdx.x - 512) * blockDim.x + t) >> 5;
        const int lane = t & 31;
        if (w >= MCODE) return;
        float4 v = *reinterpret_cast<const float4*>(e + (size_t)w * CDIM + lane * 4);
        float sq = v.x * v.x + v.y * v.y + v.z * v.z + v.w * v.w;
        uint2 h = make_uint2(packbf2(v.x, v.y), packbf2(v.z, v.w));
        *reinterpret_cast<uint2*>(ehi + (size_t)w * CDIM + lane * 4) = h;
#pragma unroll
        for (int off = 16; off; off >>= 1) sq += __shfl_xor_sync(0xffffffffu, sq, off);
        if (lane == 0) esq[w] = sq;
    }
}

// ---------------- tile MMA: warp tile 64x32, acc[4mf][4nf][4] ----------------
__device__ __forceinline__ void mma_tile(float (&acc)[4][4][4], uint32_t Ab, uint32_t Bb,
                                         const uint32_t* arow, const uint32_t* brow,
                                         int aco, int bco, int rx) {
#pragma unroll
    for (int mf = 0; mf < 4; ++mf)
#pragma unroll
        for (int nf = 0; nf < 4; ++nf)
#pragma unroll
            for (int k = 0; k < 4; ++k) acc[mf][nf][k] = 0.0f;
#pragma unroll
    for (int ks = 0; ks < 8; ++ks) {
        uint32_t b[2][4], a[4][4];
        const uint32_t sb = swzc(ks * 2 + bco, rx);
#pragma unroll
        for (int g2 = 0; g2 < 2; ++g2) ldsm_x4(b[g2], Bb + brow[g2] + sb);
        const uint32_t sa = swzc(ks * 2 + aco, rx);
#pragma unroll
        for (int mf = 0; mf < 4; ++mf) ldsm_x4(a[mf], Ab + arow[mf] + sa);
#pragma unroll
        for (int mf = 0; mf < 4; ++mf)
#pragma unroll
            for (int g2 = 0; g2 < 2; ++g2) {
                mma16816(acc[mf][2 * g2],     a[mf], &b[g2][0]);
                mma16816(acc[mf][2 * g2 + 1], a[mf], &b[g2][2]);
            }
    }
}

// ---------------- tile epilogue: dual-LSE update ----------------
__device__ __forceinline__ void epilogue(float (&acc)[4][4][4], const float* tc,
                                         const float* base2, float* mS, float* sS,
                                         float* colsm, float* cpm, float* cps,
                                         float beta2, int l, int wm, int wn, int tid,
                                         int tileIdx, int bIdx) {
    float tcv[4][2];
#pragma unroll
    for (int nf = 0; nf < 4; ++nf)
#pragma unroll
        for (int j = 0; j < 2; ++j)
            tcv[nf][j] = tc[wn * 32 + nf * 8 + 2 * (l & 3) + j];

    float g = -1e30f;
#pragma unroll
    for (int mf = 0; mf < 4; ++mf)
#pragma unroll
        for (int nf = 0; nf < 4; ++nf)
#pragma unroll
            for (int k = 0; k < 4; ++k) {
                const int ri = mf * 2 + (k >> 1);
                float v = fminf(base2[ri] + fmaf(acc[mf][nf][k], beta2, tcv[nf][k & 1]), 0.0f);
                acc[mf][nf][k] = v;
                g = fmaxf(g, v);
            }
#pragma unroll
    for (int off = 16; off; off >>= 1)
        g = fmaxf(g, __shfl_xor_sync(0xffffffffu, g, off));
#pragma unroll
    for (int mf = 0; mf < 4; ++mf)
#pragma unroll
        for (int nf = 0; nf < 4; ++nf)
#pragma unroll
            for (int k = 0; k < 4; ++k)
                acc[mf][nf][k] = ex2f(acc[mf][nf][k] - g);

    // row sums: 8 owned rows
#pragma unroll
    for (int ri = 0; ri < 8; ++ri) {
        const int mf = ri >> 1, h = ri & 1;
        float P = 0.0f;
#pragma unroll
        for (int nf = 0; nf < 4; ++nf) P += acc[mf][nf][2 * h] + acc[mf][nf][2 * h + 1];
        P += __shfl_xor_sync(0xffffffffu, P, 1);
        P += __shfl_xor_sync(0xffffffffu, P, 2);
        merge_ms(mS[ri], sS[ri], g, P);
    }
    // col sums: 8 owned cols, reduce over 8 lane-groups
    float Q[8];
#pragma unroll
    for (int nf = 0; nf < 4; ++nf)
#pragma unroll
        for (int j = 0; j < 2; ++j) {
            float q = 0.0f;
#pragma unroll
            for (int mf = 0; mf < 4; ++mf) q += acc[mf][nf][j] + acc[mf][nf][2 + j];
            Q[nf * 2 + j] = q;
        }
#pragma unroll
    for (int off = 4; off <= 16; off <<= 1)
#pragma unroll
        for (int i = 0; i < 8; ++i) Q[i] += __shfl_xor_sync(0xffffffffu, Q[i], off);
    if (l < 4) {
#pragma unroll
        for (int nf = 0; nf < 4; ++nf)
#pragma unroll
            for (int j = 0; j < 2; ++j) {
                int c = wn * 32 + nf * 8 + 2 * l + j;
                colsm[(wm * 128 + c) * 2 + 0] = g;
                colsm[(wm * 128 + c) * 2 + 1] = Q[nf * 2 + j];
            }
    }
    __syncthreads();
    if (tid < 128) {
        float m = colsm[tid * 2], s = colsm[tid * 2 + 1];
        merge_ms(m, s, colsm[(128 + tid) * 2], colsm[(128 + tid) * 2 + 1]);
        cpm[(size_t)bIdx * MCODE + tileIdx * 128 + tid] = m;
        cps[(size_t)bIdx * MCODE + tileIdx * 128 + tid] = s;
    }
}

// ---------------- single-pass pipelined kernel (R10 config) ----------------
__global__ void __launch_bounds__(256, 1)
lse_single(const __nv_bfloat16* __restrict__ Xhi, const float* __restrict__ Xsq,
           const __nv_bfloat16* __restrict__ Yhi, const float* __restrict__ Ysq,
           const float* __restrict__ lsg,
           float* __restrict__ rowm, float* __restrict__ rows,
           float* __restrict__ cpm,  float* __restrict__ cps)
{
    extern __shared__ char sraw[];
    uint32_t sb0  = smem_u32(sraw);
    uint32_t base = (sb0 + 1023) & ~1023u;
    char* smem = sraw + (base - sb0);
    float* ysq_s = reinterpret_cast<float*>(smem + OFF_YSQ);
    float* colsm = reinterpret_cast<float*>(smem + OFF_COL);
    float* redm  = reinterpret_cast<float*>(smem + OFF_REDM);
    float* reds  = reinterpret_cast<float*>(smem + OFF_REDS);

    const int tid = threadIdx.x;
    const int l   = tid & 31;
    const int w   = tid >> 5;
    const int wm  = w & 1;
    const int wn  = w >> 1;
    const int p0  = blockIdx.x * 128;

    const float ls     = lsg[0];
    const float alpha2 = -0.5f * __expf(-2.0f * ls) * 1.4426950408889634f;
    const float beta2  = -2.0f * alpha2;

    // prologue
#pragma unroll
    for (int it = 0; it < 8; ++it) {
        int u = tid + it * 256;
        int r = u >> 4, c = u & 15;
        cpasync16(base + OFF_X + r * 256 + swzc(c, r),
                  Xhi + (size_t)(p0 + r) * CDIM + c * 8);
    }
#pragma unroll
    for (int it = 0; it < 8; ++it) {
        int u = tid + it * 256;
        int r = u >> 4, c = u & 15;
        cpasync16(base + OFF_Y(0) + r * 256 + swzc(c, r), Yhi + (size_t)r * CDIM + c * 8);
    }
    cpcommit();
#pragma unroll
    for (int it = 0; it < 8; ++it) {
        int u = tid + it * 256;
        int r = u >> 4, c = u & 15;
        cpasync16(base + OFF_Y(1) + r * 256 + swzc(c, r),
                  Yhi + (size_t)(128 + r) * CDIM + c * 8);
    }
    cpcommit();
    if (tid < 128) {
        ysq_s[tid]       = alpha2 * Ysq[tid];
        ysq_s[128 + tid] = alpha2 * Ysq[128 + tid];
    }

    float base2[8];
#pragma unroll
    for (int mf = 0; mf < 4; ++mf)
#pragma unroll
        for (int h = 0; h < 2; ++h)
            base2[mf * 2 + h] = alpha2 * Xsq[p0 + wm * 64 + mf * 16 + (l >> 2) + 8 * h];

    float mS[8], sS[8];
#pragma unroll
    for (int i = 0; i < 8; ++i) { mS[i] = -1e30f; sS[i] = 0.0f; }

    const int rx  = l & 7;
    const int aco = l >> 4;
    const int bco = (l >> 3) & 1;
    uint32_t arow[4], brow[2];
#pragma unroll
    for (int mf = 0; mf < 4; ++mf)
        arow[mf] = (uint32_t)((wm * 64 + mf * 16 + (l & 15)) * 256);
#pragma unroll
    for (int g2 = 0; g2 < 2; ++g2)
        brow[g2] = (uint32_t)((wn * 32 + g2 * 16 + (l & 7) + ((l >> 4) << 3)) * 256);

    const uint32_t Ab = base + OFF_X;
    float accA[4][4][4], accB[4][4][4];

    cpwait<1>();
    __syncthreads();
    mma_tile(accA, Ab, base + OFF_Y(0), arow, brow, aco, bco, rx);
    __syncthreads();

    for (int t = 0; t < QTILES; t += 2) {
        // phase A
        if (t + 2 < QTILES) {
            const size_t q1 = (size_t)(t + 2) * 128;
#pragma unroll
            for (int it = 0; it < 8; ++it) {
                int u = tid + it * 256;
                int r = u >> 4, c = u & 15;
                cpasync16(base + OFF_Y(0) + r * 256 + swzc(c, r),
                          Yhi + (q1 + r) * CDIM + c * 8);
            }
            if (tid < 128) ysq_s[((t + 2) & 3) * 128 + tid] = alpha2 * Ysq[q1 + tid];
        }
        cpcommit();
        cpwait<1>();
        __syncthreads();
        if (t + 1 < QTILES)
            mma_tile(accB, Ab, base + OFF_Y(1), arow, brow, aco, bco, rx);
        epilogue(accA, ysq_s + (t & 3) * 128, base2, mS, sS, colsm, cpm, cps,
                 beta2, l, wm, wn, tid, t, blockIdx.x);

        // phase B
        if (t + 3 < QTILES) {
            const size_t q1 = (size_t)(t + 3) * 128;
#pragma unroll
            for (int it = 0; it < 8; ++it) {
                int u = tid + it * 256;
                int r = u >> 4, c = u & 15;
                cpasync16(base + OFF_Y(1) + r * 256 + swzc(c, r),
                          Yhi + (q1 + r) * CDIM + c * 8);
            }
            if (tid < 128) ysq_s[((t + 3) & 3) * 128 + tid] = alpha2 * Ysq[q1 + tid];
        }
        cpcommit();
        cpwait<1>();
        __syncthreads();
        if (t + 2 < QTILES)
            mma_tile(accA, Ab, base + OFF_Y(0), arow, brow, aco, bco, rx);
        if (t + 1 < QTILES)
            epilogue(accB, ysq_s + ((t + 1) & 3) * 128, base2, mS, sS, colsm, cpm, cps,
                     beta2, l, wm, wn, tid, t + 1, blockIdx.x);
    }

    // row finalization
    __syncthreads();
    if ((l & 3) == 0) {
#pragma unroll
        for (int ri = 0; ri < 8; ++ri) {
            const int mf = ri >> 1, h = ri & 1;
            int rloc = wm * 64 + mf * 16 + (l >> 2) + 8 * h;
            redm[wn * 128 + rloc] = mS[ri];
            reds[wn * 128 + rloc] = sS[ri];
        }
    }
    __syncthreads();
    if (tid < 128) {
        float m = redm[tid], s = reds[tid];
#pragma unroll
        for (int gq = 1; gq < 4; ++gq) merge_ms(m, s, redm[gq * 128 + tid], reds[gq * 128 + tid]);
        rowm[p0 + tid] = m;
        rows[p0 + tid] = s;
    }
}

// ---------------- merge column partials: two-pass (max, then sum) ----------------
__global__ void __launch_bounds__(512, 2)
colmerge(const float* __restrict__ cpm, const float* __restrict__ cps,
         float* __restrict__ cm, float* __restrict__ cs) {
    __shared__ float sm_[8][64], ss_[8][64];
    const int qi = threadIdx.x & 63;
    const int pg = threadIdx.x >> 6;
    const int q  = blockIdx.x * 64 + qi;
    float mv[16], sv[16];
    float M = -1e30f;
#pragma unroll
    for (int i = 0; i < 16; ++i) {
        int p = pg * 16 + i;
        mv[i] = __ldg(cpm + (size_t)p * MCODE + q);
        sv[i] = __ldg(cps + (size_t)p * MCODE + q);
        M = fmaxf(M, mv[i]);
    }
    float S = 0.0f;
#pragma unroll
    for (int i = 0; i < 16; ++i) S += sv[i] * ex2f(mv[i] - M);
    sm_[pg][qi] = M; ss_[pg][qi] = S;
    __syncthreads();
    if (pg == 0) {
        float M2 = M;
#pragma unroll
        for (int g = 1; g < 8; ++g) M2 = fmaxf(M2, sm_[g][qi]);
        float S2 = 0.0f;
#pragma unroll
        for (int g = 0; g < 8; ++g) S2 += ss_[g][qi] * ex2f(sm_[g][qi] - M2);
        cm[q] = M2;
        cs[q] = S2;
    }
}

// ---------------- finalize: parallel (1024 thr, 4 indep accumulators) ----------------
__global__ void __launch_bounds__(1024, 1)
finalize(const float* __restrict__ lsg, float* __restrict__ out) {
    __shared__ double red[1024];
    const int which = blockIdx.x;
    const int P     = (which == 0) ? NTOK : MCODE;
    const float* pm = (which == 0) ? g_rm : g_cm;
    const float* ps = (which == 0) ? g_rs : g_cs;
    const int t = threadIdx.x;
    double a0 = 0.0, a1 = 0.0, a2 = 0.0, a3 = 0.0;
    for (int i = t * 4; i < P; i += 4096) {
        a0 += (double)pm[i]     + (double)__log2f(ps[i]);
        a1 += (double)pm[i + 1] + (double)__log2f(ps[i + 1]);
        a2 += (double)pm[i + 2] + (double)__log2f(ps[i + 2]);
        a3 += (double)pm[i + 3] + (double)__log2f(ps[i + 3]);
    }
    red[t] = (a0 + a1) + (a2 + a3);
    __syncthreads();
    for (int st = 512; st; st >>= 1) {
        if (t < st) red[t] += red[t + st];
        __syncthreads();
    }
    if (t == 0) {
        float ls  = lsg[0];
        float cst = 0.5f * (float)CDIM * (2.0f * ls - 1.0f);
        float lg  = (which == 0) ? logf((float)MCODE) : logf((float)NTOK);
        double lse_mean = 0.6931471805599453 * (red[0] / (double)P);
        out[which] = (float)(-lse_mean) + cst + lg;
    }
}

// ---------------- launch ----------------
extern "C" void kernel_launch(void* const* d_in, const int* in_sizes, int n_in,
                              void* d_out, int out_size) {
    (void)in_sizes; (void)n_in; (void)out_size;
    const float* z   = (const float*)d_in[0];
    const float* e   = (const float*)d_in[1];
    const float* lsg = (const float*)d_in[2];
    float* out = (float*)d_out;

    float *zsq, *esq, *rm, *rs, *cpm, *cps, *cm, *cs;
    __nv_bfloat16 *zhi, *ehi;
    cudaGetSymbolAddress((void**)&zhi, g_zhi);
    cudaGetSymbolAddress((void**)&ehi, g_ehi);
    cudaGetSymbolAddress((void**)&zsq, g_zsq);
    cudaGetSymbolAddress((void**)&esq, g_esq);
    cudaGetSymbolAddress((void**)&rm,  g_rm);
    cudaGetSymbolAddress((void**)&rs,  g_rs);
    cudaGetSymbolAddress((void**)&cpm, g_cpm);
    cudaGetSymbolAddress((void**)&cps, g_cps);
    cudaGetSymbolAddress((void**)&cm,  g_cm);
    cudaGetSymbolAddress((void**)&cs,  g_cs);

    cudaFuncSetAttribute(lse_single, cudaFuncAttributeMaxDynamicSharedMemorySize, SMEM_BYTES);

    fuse_prep<<<512 + MCODE / 8, 256>>>(z, e, zhi, zsq, ehi, esq);

    lse_single<<<PTILES, 256, SMEM_BYTES>>>(zhi, zsq, ehi, esq, lsg, rm, rs, cpm, cps);

    colmerge<<<MCODE / 64, 512>>>(cpm, cps, cm, cs);
    finalize<<<2, 1024>>>(lsg, out);
}

// round 15
// speedup vs baseline: 1.1083x; 1.1083x over previous
#include <cuda_runtime.h>
#include <cuda_bf16.h>
#include <math.h>
#include <stdint.h>

// Problem constants (dataset-fixed: z[16,128,32,32], e[8192,128], log_sigma[1])
#define NTOK  16384
#define MCODE 8192
#define CDIM  128
#define BDIM  16
#define HWDIM 1024
#define PTILES (NTOK / 128)     /* 128 CTAs, 128 rows each */
#define QTILES (MCODE / 128)    /* 64 streamed q tiles */

// ---------------- device scratch ----------------
__device__ __nv_bfloat16 g_zhi[(size_t)NTOK * CDIM];
__device__ __nv_bfloat16 g_ehi[(size_t)MCODE * CDIM];
__device__ float g_zsq[NTOK], g_esq[MCODE];
__device__ float g_rm[NTOK],  g_rs[NTOK];
__device__ float g_cpm[(size_t)PTILES * MCODE];
__device__ float g_cps[(size_t)PTILES * MCODE];
__device__ float g_cm[MCODE], g_cs[MCODE];

// ---------------- helpers ----------------
__device__ __forceinline__ uint32_t smem_u32(const void* p) {
    uint32_t a;
    asm("{ .reg .u64 t; cvta.to.shared.u64 t, %1; cvt.u32.u64 %0, t; }" : "=r"(a) : "l"(p));
    return a;
}
__device__ __forceinline__ float ex2f(float x) {
    float r; asm("ex2.approx.ftz.f32 %0, %1;" : "=f"(r) : "f"(x)); return r;
}
__device__ __forceinline__ void merge_ms(float& m, float& s, float m2, float s2) {
    float e = ex2f(-fabsf(m - m2));
    if (m >= m2) { s = s + s2 * e; }
    else         { s = s2 + s * e; m = m2; }
}
__device__ __forceinline__ void cpasync16(uint32_t dst, const void* src) {
    asm volatile("cp.async.cg.shared.global [%0], [%1], 16;" :: "r"(dst), "l"(src) : "memory");
}
__device__ __forceinline__ void cpcommit() {
    asm volatile("cp.async.commit_group;" ::: "memory");
}
template <int N> __device__ __forceinline__ void cpwait() {
    asm volatile("cp.async.wait_group %0;" :: "n"(N) : "memory");
}
__device__ __forceinline__ void ldsm_x4(uint32_t* r, uint32_t addr) {
    asm volatile("ldmatrix.sync.aligned.m8n8.x4.shared.b16 {%0,%1,%2,%3}, [%4];"
                 : "=r"(r[0]), "=r"(r[1]), "=r"(r[2]), "=r"(r[3]) : "r"(addr));
}
__device__ __forceinline__ void mma16816(float* d, const uint32_t* a, const uint32_t* b) {
    asm volatile(
        "mma.sync.aligned.m16n8k16.row.col.f32.bf16.bf16.f32 "
        "{%0,%1,%2,%3}, {%4,%5,%6,%7}, {%8,%9}, {%0,%1,%2,%3};"
        : "+f"(d[0]), "+f"(d[1]), "+f"(d[2]), "+f"(d[3])
        : "r"(a[0]), "r"(a[1]), "r"(a[2]), "r"(a[3]), "r"(b[0]), "r"(b[1]));
}
__device__ __forceinline__ uint32_t packbf2(float a, float b) {
    __nv_bfloat162 t = __floats2bfloat162_rn(a, b);
    return *reinterpret_cast<uint32_t*>(&t);
}

// ---------------- smem layout ----------------
#define OFF_X      0                      /* 128*256 = 32KB             */
#define OFF_Y(b)   (32768 + (b) * 32768)  /* two 32KB Y buffers         */
#define OFF_YSQ    98304                  /* 4 slots x 128 floats = 2KB */
#define OFF_COL    100352                 /* 2*128*2 floats = 2KB       */
#define OFF_REDM   102400                 /* 4*128 floats = 2KB         */
#define OFF_REDS   104448                 /* 4*128 floats = 2KB         */
#define SMEM_BYTES (106496 + 1024)

__device__ __forceinline__ uint32_t swzc(int c, int r) {
    return (uint32_t)(((c >> 3) << 7) + ((((c & 7) ^ (r & 7))) << 4));
}

// ---------------- fused prep: one launch for z + e ----------------
__global__ void fuse_prep(const float* __restrict__ z, const float* __restrict__ e,
                          __nv_bfloat16* __restrict__ zhi, float* __restrict__ zsq,
                          __nv_bfloat16* __restrict__ ehi, float* __restrict__ esq) {
    __shared__ float tile[32 * 129];
    const int t = threadIdx.x;
    if (blockIdx.x < 512) {
        const int b    = blockIdx.x >> 5;
        const int hw0  = (blockIdx.x & 31) * 32;
        const int lane = t & 31;
#pragma unroll
        for (int it = 0; it < 16; ++it) {
            int c = (t >> 5) + it * 8;
            tile[lane * 129 + c] = z[(size_t)b * (CDIM * HWDIM) + (size_t)c * HWDIM + hw0 + lane];
        }
        __syncthreads();
        const int tloc = t >> 3;
        const int c0   = (t & 7) * 16;
        const int n    = b * HWDIM + hw0 + tloc;
        float sq = 0.0f;
        uint32_t hp[8];
#pragma unroll
        for (int i = 0; i < 8; ++i) {
            float a = tile[tloc * 129 + c0 + 2 * i];
            float c = tile[tloc * 129 + c0 + 2 * i + 1];
            sq += a * a + c * c;
            hp[i] = packbf2(a, c);
        }
        uint4* dh = reinterpret_cast<uint4*>(zhi + (size_t)n * CDIM + c0);
        dh[0] = make_uint4(hp[0], hp[1], hp[2], hp[3]);
        dh[1] = make_uint4(hp[4], hp[5], hp[6], hp[7]);
#pragma unroll
        for (int off = 1; off <= 4; off <<= 1) sq += __shfl_xor_sync(0xffffffffu, sq, off);
        if ((t & 7) == 0) zsq[n] = sq;
    } else {
        const int w    = ((blockIdx.x - 512) * blockDim.x + t) >> 5;
        const int lane = t & 31;
        if (w >= MCODE) return;
        float4 v = *reinterpret_cast<const float4*>(e + (size_t)w * CDIM + lane * 4);
        float sq = v.x * v.x + v.y * v.y + v.z * v.z + v.w * v.w;
        uint2 h = make_uint2(packbf2(v.x, v.y), packbf2(v.z, v.w));
        *reinterpret_cast<uint2*>(ehi + (size_t)w * CDIM + lane * 4) = h;
#pragma unroll
        for (int off = 16; off; off >>= 1) sq += __shfl_xor_sync(0xffffffffu, sq, off);
        if (lane == 0) esq[w] = sq;
    }
}

// ---------------- tile MMA: warp tile 64x32, acc[4mf][4nf][4] ----------------
__device__ __forceinline__ void mma_tile(float (&acc)[4][4][4], uint32_t Ab, uint32_t Bb,
                                         const uint32_t* arow, const uint32_t* brow,
                                         int aco, int bco, int rx) {
#pragma unroll
    for (int mf = 0; mf < 4; ++mf)
#pragma unroll
        for (int nf = 0; nf < 4; ++nf)
#pragma unroll
            for (int k = 0; k < 4; ++k) acc[mf][nf][k] = 0.0f;
#pragma unroll
    for (int ks = 0; ks < 8; ++ks) {
        uint32_t b[2][4], a[4][4];
        const uint32_t sb = swzc(ks * 2 + bco, rx);
#pragma unroll
        for (int g2 = 0; g2 < 2; ++g2) ldsm_x4(b[g2], Bb + brow[g2] + sb);
        const uint32_t sa = swzc(ks * 2 + aco, rx);
#pragma unroll
        for (int mf = 0; mf < 4; ++mf) ldsm_x4(a[mf], Ab + arow[mf] + sa);
#pragma unroll
        for (int mf = 0; mf < 4; ++mf)
#pragma unroll
            for (int g2 = 0; g2 < 2; ++g2) {
                mma16816(acc[mf][2 * g2],     a[mf], &b[g2][0]);
                mma16816(acc[mf][2 * g2 + 1], a[mf], &b[g2][2]);
            }
    }
}

// ---------------- tile epilogue: dual-LSE update ----------------
__device__ __forceinline__ void epilogue(float (&acc)[4][4][4], const float* tc,
                                         const float* base2, float* mS, float* sS,
                                         float* colsm, float* cpm, float* cps,
                                         float beta2, int l, int wm, int wn, int tid,
                                         int tileIdx, int bIdx) {
    float tcv[4][2];
#pragma unroll
    for (int nf = 0; nf < 4; ++nf)
#pragma unroll
        for (int j = 0; j < 2; ++j)
            tcv[nf][j] = tc[wn * 32 + nf * 8 + 2 * (l & 3) + j];

    float g = -1e30f;
#pragma unroll
    for (int mf = 0; mf < 4; ++mf)
#pragma unroll
        for (int nf = 0; nf < 4; ++nf)
#pragma unroll
            for (int k = 0; k < 4; ++k) {
                const int ri = mf * 2 + (k >> 1);
                float v = fminf(base2[ri] + fmaf(acc[mf][nf][k], beta2, tcv[nf][k & 1]), 0.0f);
                acc[mf][nf][k] = v;
                g = fmaxf(g, v);
            }
#pragma unroll
    for (int off = 16; off; off >>= 1)
        g = fmaxf(g, __shfl_xor_sync(0xffffffffu, g, off));
#pragma unroll
    for (int mf = 0; mf < 4; ++mf)
#pragma unroll
        for (int nf = 0; nf < 4; ++nf)
#pragma unroll
            for (int k = 0; k < 4; ++k)
                acc[mf][nf][k] = ex2f(acc[mf][nf][k] - g);

    // row sums: 8 owned rows
#pragma unroll
    for (int ri = 0; ri < 8; ++ri) {
        const int mf = ri >> 1, h = ri & 1;
        float P = 0.0f;
#pragma unroll
        for (int nf = 0; nf < 4; ++nf) P += acc[mf][nf][2 * h] + acc[mf][nf][2 * h + 1];
        P += __shfl_xor_sync(0xffffffffu, P, 1);
        P += __shfl_xor_sync(0xffffffffu, P, 2);
        merge_ms(mS[ri], sS[ri], g, P);
    }
    // col sums: 8 owned cols, reduce over 8 lane-groups
    float Q[8];
#pragma unroll
    for (int nf = 0; nf < 4; ++nf)
#pragma unroll
        for (int j = 0; j < 2; ++j) {
            float q = 0.0f;
#pragma unroll
            for (int mf = 0; mf < 4; ++mf) q += acc[mf][nf][j] + acc[mf][nf][2 + j];
            Q[nf * 2 + j] = q;
        }
#pragma unroll
    for (int off = 4; off <= 16; off <<= 1)
#pragma unroll
        for (int i = 0; i < 8; ++i) Q[i] += __shfl_xor_sync(0xffffffffu, Q[i], off);
    if (l < 4) {
#pragma unroll
        for (int nf = 0; nf < 4; ++nf)
#pragma unroll
            for (int j = 0; j < 2; ++j) {
                int c = wn * 32 + nf * 8 + 2 * l + j;
                colsm[(wm * 128 + c) * 2 + 0] = g;
                colsm[(wm * 128 + c) * 2 + 1] = Q[nf * 2 + j];
            }
    }
    __syncthreads();
    if (tid < 128) {
        float m = colsm[tid * 2], s = colsm[tid * 2 + 1];
        merge_ms(m, s, colsm[(128 + tid) * 2], colsm[(128 + tid) * 2 + 1]);
        cpm[(size_t)bIdx * MCODE + tileIdx * 128 + tid] = m;
        cps[(size_t)bIdx * MCODE + tileIdx * 128 + tid] = s;
    }
}

// ---------------- single-pass pipelined kernel (R10 config) ----------------
__global__ void __launch_bounds__(256, 1)
lse_single(const __nv_bfloat16* __restrict__ Xhi, const float* __restrict__ Xsq,
           const __nv_bfloat16* __restrict__ Yhi, const float* __restrict__ Ysq,
           const float* __restrict__ lsg,
           float* __restrict__ rowm, float* __restrict__ rows,
           float* __restrict__ cpm,  float* __restrict__ cps)
{
    extern __shared__ char sraw[];
    uint32_t sb0  = smem_u32(sraw);
    uint32_t base = (sb0 + 1023) & ~1023u;
    char* smem = sraw + (base - sb0);
    float* ysq_s = reinterpret_cast<float*>(smem + OFF_YSQ);
    float* colsm = reinterpret_cast<float*>(smem + OFF_COL);
    float* redm  = reinterpret_cast<float*>(smem + OFF_REDM);
    float* reds  = reinterpret_cast<float*>(smem + OFF_REDS);

    const int tid = threadIdx.x;
    const int l   = tid & 31;
    const int w   = tid >> 5;
    const int wm  = w & 1;
    const int wn  = w >> 1;
    const int p0  = blockIdx.x * 128;

    const float ls     = lsg[0];
    const float alpha2 = -0.5f * __expf(-2.0f * ls) * 1.4426950408889634f;
    const float beta2  = -2.0f * alpha2;

    // prologue
#pragma unroll
    for (int it = 0; it < 8; ++it) {
        int u = tid + it * 256;
        int r = u >> 4, c = u & 15;
        cpasync16(base + OFF_X + r * 256 + swzc(c, r),
                  Xhi + (size_t)(p0 + r) * CDIM + c * 8);
    }
#pragma unroll
    for (int it = 0; it < 8; ++it) {
        int u = tid + it * 256;
        int r = u >> 4, c = u & 15;
        cpasync16(base + OFF_Y(0) + r * 256 + swzc(c, r), Yhi + (size_t)r * CDIM + c * 8);
    }
    cpcommit();
#pragma unroll
    for (int it = 0; it < 8; ++it) {
        int u = tid + it * 256;
        int r = u >> 4, c = u & 15;
        cpasync16(base + OFF_Y(1) + r * 256 + swzc(c, r),
                  Yhi + (size_t)(128 + r) * CDIM + c * 8);
    }
    cpcommit();
    if (tid < 128) {
        ysq_s[tid]       = alpha2 * Ysq[tid];
        ysq_s[128 + tid] = alpha2 * Ysq[128 + tid];
    }

    float base2[8];
#pragma unroll
    for (int mf = 0; mf < 4; ++mf)
#pragma unroll
        for (int h = 0; h < 2; ++h)
            base2[mf * 2 + h] = alpha2 * Xsq[p0 + wm * 64 + mf * 16 + (l >> 2) + 8 * h];

    float mS[8], sS[8];
#pragma unroll
    for (int i = 0; i < 8; ++i) { mS[i] = -1e30f; sS[i] = 0.0f; }

    const int rx  = l & 7;
    const int aco = l >> 4;
    const int bco = (l >> 3) & 1;
    uint32_t arow[4], brow[2];
#pragma unroll
    for (int mf = 0; mf < 4; ++mf)
        arow[mf] = (uint32_t)((wm * 64 + mf * 16 + (l & 15)) * 256);
#pragma unroll
    for (int g2 = 0; g2 < 2; ++g2)
        brow[g2] = (uint32_t)((wn * 32 + g2 * 16 + (l & 7) + ((l >> 4) << 3)) * 256);

    const uint32_t Ab = base + OFF_X;
    float accA[4][4][4], accB[4][4][4];

    cpwait<1>();
    __syncthreads();
    mma_tile(accA, Ab, base + OFF_Y(0), arow, brow, aco, bco, rx);
    __syncthreads();

    for (int t = 0; t < QTILES; t += 2) {
        // phase A
        if (t + 2 < QTILES) {
            const size_t q1 = (size_t)(t + 2) * 128;
#pragma unroll
            for (int it = 0; it < 8; ++it) {
                int u = tid + it * 256;
                int r = u >> 4, c = u & 15;
                cpasync16(base + OFF_Y(0) + r * 256 + swzc(c, r),
                          Yhi + (q1 + r) * CDIM + c * 8);
            }
            if (tid < 128) ysq_s[((t + 2) & 3) * 128 + tid] = alpha2 * Ysq[q1 + tid];
        }
        cpcommit();
        cpwait<1>();
        __syncthreads();
        if (t + 1 < QTILES)
            mma_tile(accB, Ab, base + OFF_Y(1), arow, brow, aco, bco, rx);
        epilogue(accA, ysq_s + (t & 3) * 128, base2, mS, sS, colsm, cpm, cps,
                 beta2, l, wm, wn, tid, t, blockIdx.x);

        // phase B
        if (t + 3 < QTILES) {
            const size_t q1 = (size_t)(t + 3) * 128;
#pragma unroll
            for (int it = 0; it < 8; ++it) {
                int u = tid + it * 256;
                int r = u >> 4, c = u & 15;
                cpasync16(base + OFF_Y(1) + r * 256 + swzc(c, r),
                          Yhi + (q1 + r) * CDIM + c * 8);
            }
            if (tid < 128) ysq_s[((t + 3) & 3) * 128 + tid] = alpha2 * Ysq[q1 + tid];
        }
        cpcommit();
        cpwait<1>();
        __syncthreads();
        if (t + 2 < QTILES)
            mma_tile(accA, Ab, base + OFF_Y(0), arow, brow, aco, bco, rx);
        if (t + 1 < QTILES)
            epilogue(accB, ysq_s + ((t + 1) & 3) * 128, base2, mS, sS, colsm, cpm, cps,
                     beta2, l, wm, wn, tid, t + 1, blockIdx.x);
    }

    // row finalization
    __syncthreads();
    if ((l & 3) == 0) {
#pragma unroll
        for (int ri = 0; ri < 8; ++ri) {
            const int mf = ri >> 1, h = ri & 1;
            int rloc = wm * 64 + mf * 16 + (l >> 2) + 8 * h;
            redm[wn * 128 + rloc] = mS[ri];
            reds[wn * 128 + rloc] = sS[ri];
        }
    }
    __syncthreads();
    if (tid < 128) {
        float m = redm[tid], s = reds[tid];
#pragma unroll
        for (int gq = 1; gq < 4; ++gq) merge_ms(m, s, redm[gq * 128 + tid], reds[gq * 128 + tid]);
        rowm[p0 + tid] = m;
        rows[p0 + tid] = s;
    }
}

// ---------------- merge column partials: two-pass (max, then sum) ----------------
__global__ void __launch_bounds__(512, 2)
colmerge(const float* __restrict__ cpm, const float* __restrict__ cps,
         float* __restrict__ cm, float* __restrict__ cs) {
    __shared__ float sm_[8][64], ss_[8][64];
    const int qi = threadIdx.x & 63;
    const int pg = threadIdx.x >> 6;
    const int q  = blockIdx.x * 64 + qi;
    float mv[16], sv[16];
    float M = -1e30f;
#pragma unroll
    for (int i = 0; i < 16; ++i) {
        int p = pg * 16 + i;
        mv[i] = __ldg(cpm + (size_t)p * MCODE + q);
        sv[i] = __ldg(cps + (size_t)p * MCODE + q);
        M = fmaxf(M, mv[i]);
    }
    float S = 0.0f;
#pragma unroll
    for (int i = 0; i < 16; ++i) S += sv[i] * ex2f(mv[i] - M);
    sm_[pg][qi] = M; ss_[pg][qi] = S;
    __syncthreads();
    if (pg == 0) {
        float M2 = M;
#pragma unroll
        for (int g = 1; g < 8; ++g) M2 = fmaxf(M2, sm_[g][qi]);
        float S2 = 0.0f;
#pragma unroll
        for (int g = 0; g < 8; ++g) S2 += ss_[g][qi] * ex2f(sm_[g][qi] - M2);
        cm[q] = M2;
        cs[q] = S2;
    }
}

// ---------------- finalize: all-float reduction (FP64 only for the final mean) ----------------
__global__ void __launch_bounds__(1024, 1)
finalize(const float* __restrict__ lsg, float* __restrict__ out) {
    __shared__ float red[1024];
    const int which = blockIdx.x;
    const int P     = (which == 0) ? NTOK : MCODE;
    const float* pm = (which == 0) ? g_rm : g_cm;
    const float* ps = (which == 0) ? g_rs : g_cs;
    const int t = threadIdx.x;
    float a0 = 0.0f, a1 = 0.0f, a2 = 0.0f, a3 = 0.0f;
    for (int i = t * 4; i < P; i += 4096) {
        a0 += pm[i]     + __log2f(ps[i]);
        a1 += pm[i + 1] + __log2f(ps[i + 1]);
        a2 += pm[i + 2] + __log2f(ps[i + 2]);
        a3 += pm[i + 3] + __log2f(ps[i + 3]);
    }
    red[t] = (a0 + a1) + (a2 + a3);
    __syncthreads();
    for (int st = 512; st; st >>= 1) {
        if (t < st) red[t] += red[t + st];
        __syncthreads();
    }
    if (t == 0) {
        float ls  = lsg[0];
        float cst = 0.5f * (float)CDIM * (2.0f * ls - 1.0f);
        float lg  = (which == 0) ? logf((float)MCODE) : logf((float)NTOK);
        double lse_mean = 0.6931471805599453 * ((double)red[0] / (double)P);
        out[which] = (float)(-lse_mean) + cst + lg;
    }
}

// ---------------- launch ----------------
extern "C" void kernel_launch(void* const* d_in, const int* in_sizes, int n_in,
                              void* d_out, int out_size) {
    (void)in_sizes; (void)n_in; (void)out_size;
    const float* z   = (const float*)d_in[0];
    const float* e   = (const float*)d_in[1];
    const float* lsg = (const float*)d_in[2];
    float* out = (float*)d_out;

    float *zsq, *esq, *rm, *rs, *cpm, *cps, *cm, *cs;
    __nv_bfloat16 *zhi, *ehi;
    cudaGetSymbolAddress((void**)&zhi, g_zhi);
    cudaGetSymbolAddress((void**)&ehi, g_ehi);
    cudaGetSymbolAddress((void**)&zsq, g_zsq);
    cudaGetSymbolAddress((void**)&esq, g_esq);
    cudaGetSymbolAddress((void**)&rm,  g_rm);
    cudaGetSymbolAddress((void**)&rs,  g_rs);
    cudaGetSymbolAddress((void**)&cpm, g_cpm);
    cudaGetSymbolAddress((void**)&cps, g_cps);
    cudaGetSymbolAddress((void**)&cm,  g_cm);
    cudaGetSymbolAddress((void**)&cs,  g_cs);

    cudaFuncSetAttribute(lse_single, cudaFuncAttributeMaxDynamicSharedMemorySize, SMEM_BYTES);

    fuse_prep<<<512 + MCODE / 8, 256>>>(z, e, zhi, zsq, ehi, esq);

    lse_single<<<PTILES, 256, SMEM_BYTES>>>(zhi, zsq, ehi, esq, lsg, rm, rs, cpm, cps);

    colmerge<<<MCODE / 64, 512>>>(cpm, cps, cm, cs);
    finalize<<<2, 1024>>>(lsg, out);
}

// round 16
// speedup vs baseline: 1.1246x; 1.0147x over previous
#include <cuda_runtime.h>
#include <cuda_bf16.h>
#include <math.h>
#include <stdint.h>

// Problem constants (dataset-fixed: z[16,128,32,32], e[8192,128], log_sigma[1])
#define NTOK  16384
#define MCODE 8192
#define CDIM  128
#define BDIM  16
#define HWDIM 1024
#define PTILES (NTOK / 128)     /* 128 CTAs, 128 rows each */
#define QTILES (MCODE / 128)    /* 64 streamed q tiles */

// ---------------- device scratch ----------------
__device__ __nv_bfloat16 g_zhi[(size_t)NTOK * CDIM];
__device__ __nv_bfloat16 g_ehi[(size_t)MCODE * CDIM];
__device__ float g_zsq[NTOK], g_esq[MCODE];
__device__ float g_rm[NTOK],  g_rs[NTOK];
__device__ float g_cpm[(size_t)PTILES * MCODE];
__device__ float g_cps[(size_t)PTILES * MCODE];
__device__ float g_part1[32];    // row-LSE partial sums (32 blocks)
__device__ float g_part2[128];   // col-LSE partial sums (128 blocks)

// ---------------- helpers ----------------
__device__ __forceinline__ uint32_t smem_u32(const void* p) {
    uint32_t a;
    asm("{ .reg .u64 t; cvta.to.shared.u64 t, %1; cvt.u32.u64 %0, t; }" : "=r"(a) : "l"(p));
    return a;
}
__device__ __forceinline__ float ex2f(float x) {
    float r; asm("ex2.approx.ftz.f32 %0, %1;" : "=f"(r) : "f"(x)); return r;
}
__device__ __forceinline__ void merge_ms(float& m, float& s, float m2, float s2) {
    float e = ex2f(-fabsf(m - m2));
    if (m >= m2) { s = s + s2 * e; }
    else         { s = s2 + s * e; m = m2; }
}
__device__ __forceinline__ void cpasync16(uint32_t dst, const void* src) {
    asm volatile("cp.async.cg.shared.global [%0], [%1], 16;" :: "r"(dst), "l"(src) : "memory");
}
__device__ __forceinline__ void cpcommit() {
    asm volatile("cp.async.commit_group;" ::: "memory");
}
template <int N> __device__ __forceinline__ void cpwait() {
    asm volatile("cp.async.wait_group %0;" :: "n"(N) : "memory");
}
__device__ __forceinline__ void ldsm_x4(uint32_t* r, uint32_t addr) {
    asm volatile("ldmatrix.sync.aligned.m8n8.x4.shared.b16 {%0,%1,%2,%3}, [%4];"
                 : "=r"(r[0]), "=r"(r[1]), "=r"(r[2]), "=r"(r[3]) : "r"(addr));
}
__device__ __forceinline__ void mma16816(float* d, const uint32_t* a, const uint32_t* b) {
    asm volatile(
        "mma.sync.aligned.m16n8k16.row.col.f32.bf16.bf16.f32 "
        "{%0,%1,%2,%3}, {%4,%5,%6,%7}, {%8,%9}, {%0,%1,%2,%3};"
        : "+f"(d[0]), "+f"(d[1]), "+f"(d[2]), "+f"(d[3])
        : "r"(a[0]), "r"(a[1]), "r"(a[2]), "r"(a[3]), "r"(b[0]), "r"(b[1]));
}
__device__ __forceinline__ uint32_t packbf2(float a, float b) {
    __nv_bfloat162 t = __floats2bfloat162_rn(a, b);
    return *reinterpret_cast<uint32_t*>(&t);
}

// ---------------- smem layout ----------------
#define OFF_X      0                      /* 128*256 = 32KB             */
#define OFF_Y(b)   (32768 + (b) * 32768)  /* two 32KB Y buffers         */
#define OFF_YSQ    98304                  /* 4 slots x 128 floats = 2KB */
#define OFF_COL    100352                 /* 2*128*2 floats = 2KB       */
#define OFF_REDM   102400                 /* 4*128 floats = 2KB         */
#define OFF_REDS   104448                 /* 4*128 floats = 2KB         */
#define SMEM_BYTES (106496 + 1024)

__device__ __forceinline__ uint32_t swzc(int c, int r) {
    return (uint32_t)(((c >> 3) << 7) + ((((c & 7) ^ (r & 7))) << 4));
}

// ---------------- fused prep: one launch for z + e ----------------
__global__ void fuse_prep(const float* __restrict__ z, const float* __restrict__ e,
                          __nv_bfloat16* __restrict__ zhi, float* __restrict__ zsq,
                          __nv_bfloat16* __restrict__ ehi, float* __restrict__ esq) {
    __shared__ float tile[32 * 129];
    const int t = threadIdx.x;
    if (blockIdx.x < 512) {
        const int b    = blockIdx.x >> 5;
        const int hw0  = (blockIdx.x & 31) * 32;
        const int lane = t & 31;
#pragma unroll
        for (int it = 0; it < 16; ++it) {
            int c = (t >> 5) + it * 8;
            tile[lane * 129 + c] = z[(size_t)b * (CDIM * HWDIM) + (size_t)c * HWDIM + hw0 + lane];
        }
        __syncthreads();
        const int tloc = t >> 3;
        const int c0   = (t & 7) * 16;
        const int n    = b * HWDIM + hw0 + tloc;
        float sq = 0.0f;
        uint32_t hp[8];
#pragma unroll
        for (int i = 0; i < 8; ++i) {
            float a = tile[tloc * 129 + c0 + 2 * i];
            float c = tile[tloc * 129 + c0 + 2 * i + 1];
            sq += a * a + c * c;
            hp[i] = packbf2(a, c);
        }
        uint4* dh = reinterpret_cast<uint4*>(zhi + (size_t)n * CDIM + c0);
        dh[0] = make_uint4(hp[0], hp[1], hp[2], hp[3]);
        dh[1] = make_uint4(hp[4], hp[5], hp[6], hp[7]);
#pragma unroll
        for (int off = 1; off <= 4; off <<= 1) sq += __shfl_xor_sync(0xffffffffu, sq, off);
        if ((t & 7) == 0) zsq[n] = sq;
    } else {
        const int w    = ((blockIdx.x - 512) * blockDim.x + t) >> 5;
        const int lane = t & 31;
        if (w >= MCODE) return;
        float4 v = *reinterpret_cast<const float4*>(e + (size_t)w * CDIM + lane * 4);
        float sq = v.x * v.x + v.y * v.y + v.z * v.z + v.w * v.w;
        uint2 h = make_uint2(packbf2(v.x, v.y), packbf2(v.z, v.w));
        *reinterpret_cast<uint2*>(ehi + (size_t)w * CDIM + lane * 4) = h;
#pragma unroll
        for (int off = 16; off; off >>= 1) sq += __shfl_xor_sync(0xffffffffu, sq, off);
        if (lane == 0) esq[w] = sq;
    }
}

// ---------------- tile MMA: warp tile 64x32, acc[4mf][4nf][4] ----------------
__device__ __forceinline__ void mma_tile(float (&acc)[4][4][4], uint32_t Ab, uint32_t Bb,
                                         const uint32_t* arow, const uint32_t* brow,
                                         int aco, int bco, int rx) {
#pragma unroll
    for (int mf = 0; mf < 4; ++mf)
#pragma unroll
        for (int nf = 0; nf < 4; ++nf)
#pragma unroll
            for (int k = 0; k < 4; ++k) acc[mf][nf][k] = 0.0f;
#pragma unroll
    for (int ks = 0; ks < 8; ++ks) {
        uint32_t b[2][4], a[4][4];
        const uint32_t sb = swzc(ks * 2 + bco, rx);
#pragma unroll
        for (int g2 = 0; g2 < 2; ++g2) ldsm_x4(b[g2], Bb + brow[g2] + sb);
        const uint32_t sa = swzc(ks * 2 + aco, rx);
#pragma unroll
        for (int mf = 0; mf < 4; ++mf) ldsm_x4(a[mf], Ab + arow[mf] + sa);
#pragma unroll
        for (int mf = 0; mf < 4; ++mf)
#pragma unroll
            for (int g2 = 0; g2 < 2; ++g2) {
                mma16816(acc[mf][2 * g2],     a[mf], &b[g2][0]);
                mma16816(acc[mf][2 * g2 + 1], a[mf], &b[g2][2]);
            }
    }
}

// ---------------- tile epilogue: dual-LSE update ----------------
__device__ __forceinline__ void epilogue(float (&acc)[4][4][4], const float* tc,
                                         const float* base2, float* mS, float* sS,
                                         float* colsm, float* cpm, float* cps,
                                         float beta2, int l, int wm, int wn, int tid,
                                         int tileIdx, int bIdx) {
    float tcv[4][2];
#pragma unroll
    for (int nf = 0; nf < 4; ++nf)
#pragma unroll
        for (int j = 0; j < 2; ++j)
            tcv[nf][j] = tc[wn * 32 + nf * 8 + 2 * (l & 3) + j];

    float g = -1e30f;
#pragma unroll
    for (int mf = 0; mf < 4; ++mf)
#pragma unroll
        for (int nf = 0; nf < 4; ++nf)
#pragma unroll
            for (int k = 0; k < 4; ++k) {
                const int ri = mf * 2 + (k >> 1);
                float v = fminf(base2[ri] + fmaf(acc[mf][nf][k], beta2, tcv[nf][k & 1]), 0.0f);
                acc[mf][nf][k] = v;
                g = fmaxf(g, v);
            }
#pragma unroll
    for (int off = 16; off; off >>= 1)
        g = fmaxf(g, __shfl_xor_sync(0xffffffffu, g, off));
#pragma unroll
    for (int mf = 0; mf < 4; ++mf)
#pragma unroll
        for (int nf = 0; nf < 4; ++nf)
#pragma unroll
            for (int k = 0; k < 4; ++k)
                acc[mf][nf][k] = ex2f(acc[mf][nf][k] - g);

    // row sums: 8 owned rows
#pragma unroll
    for (int ri = 0; ri < 8; ++ri) {
        const int mf = ri >> 1, h = ri & 1;
        float P = 0.0f;
#pragma unroll
        for (int nf = 0; nf < 4; ++nf) P += acc[mf][nf][2 * h] + acc[mf][nf][2 * h + 1];
        P += __shfl_xor_sync(0xffffffffu, P, 1);
        P += __shfl_xor_sync(0xffffffffu, P, 2);
        merge_ms(mS[ri], sS[ri], g, P);
    }
    // col sums: 8 owned cols, reduce over 8 lane-groups
    float Q[8];
#pragma unroll
    for (int nf = 0; nf < 4; ++nf)
#pragma unroll
        for (int j = 0; j < 2; ++j) {
            float q = 0.0f;
#pragma unroll
            for (int mf = 0; mf < 4; ++mf) q += acc[mf][nf][j] + acc[mf][nf][2 + j];
            Q[nf * 2 + j] = q;
        }
#pragma unroll
    for (int off = 4; off <= 16; off <<= 1)
#pragma unroll
        for (int i = 0; i < 8; ++i) Q[i] += __shfl_xor_sync(0xffffffffu, Q[i], off);
    if (l < 4) {
#pragma unroll
        for (int nf = 0; nf < 4; ++nf)
#pragma unroll
            for (int j = 0; j < 2; ++j) {
                int c = wn * 32 + nf * 8 + 2 * l + j;
                colsm[(wm * 128 + c) * 2 + 0] = g;
                colsm[(wm * 128 + c) * 2 + 1] = Q[nf * 2 + j];
            }
    }
    __syncthreads();
    if (tid < 128) {
        float m = colsm[tid * 2], s = colsm[tid * 2 + 1];
        merge_ms(m, s, colsm[(128 + tid) * 2], colsm[(128 + tid) * 2 + 1]);
        cpm[(size_t)bIdx * MCODE + tileIdx * 128 + tid] = m;
        cps[(size_t)bIdx * MCODE + tileIdx * 128 + tid] = s;
    }
}

// ---------------- single-pass pipelined kernel (R10 config) ----------------
__global__ void __launch_bounds__(256, 1)
lse_single(const __nv_bfloat16* __restrict__ Xhi, const float* __restrict__ Xsq,
           const __nv_bfloat16* __restrict__ Yhi, const float* __restrict__ Ysq,
           const float* __restrict__ lsg,
           float* __restrict__ rowm, float* __restrict__ rows,
           float* __restrict__ cpm,  float* __restrict__ cps)
{
    extern __shared__ char sraw[];
    uint32_t sb0  = smem_u32(sraw);
    uint32_t base = (sb0 + 1023) & ~1023u;
    char* smem = sraw + (base - sb0);
    float* ysq_s = reinterpret_cast<float*>(smem + OFF_YSQ);
    float* colsm = reinterpret_cast<float*>(smem + OFF_COL);
    float* redm  = reinterpret_cast<float*>(smem + OFF_REDM);
    float* reds  = reinterpret_cast<float*>(smem + OFF_REDS);

    const int tid = threadIdx.x;
    const int l   = tid & 31;
    const int w   = tid >> 5;
    const int wm  = w & 1;
    const int wn  = w >> 1;
    const int p0  = blockIdx.x * 128;

    const float ls     = lsg[0];
    const float alpha2 = -0.5f * __expf(-2.0f * ls) * 1.4426950408889634f;
    const float beta2  = -2.0f * alpha2;

    // prologue
#pragma unroll
    for (int it = 0; it < 8; ++it) {
        int u = tid + it * 256;
        int r = u >> 4, c = u & 15;
        cpasync16(base + OFF_X + r * 256 + swzc(c, r),
                  Xhi + (size_t)(p0 + r) * CDIM + c * 8);
    }
#pragma unroll
    for (int it = 0; it < 8; ++it) {
        int u = tid + it * 256;
        int r = u >> 4, c = u & 15;
        cpasync16(base + OFF_Y(0) + r * 256 + swzc(c, r), Yhi + (size_t)r * CDIM + c * 8);
    }
    cpcommit();
#pragma unroll
    for (int it = 0; it < 8; ++it) {
        int u = tid + it * 256;
        int r = u >> 4, c = u & 15;
        cpasync16(base + OFF_Y(1) + r * 256 + swzc(c, r),
                  Yhi + (size_t)(128 + r) * CDIM + c * 8);
    }
    cpcommit();
    if (tid < 128) {
        ysq_s[tid]       = alpha2 * Ysq[tid];
        ysq_s[128 + tid] = alpha2 * Ysq[128 + tid];
    }

    float base2[8];
#pragma unroll
    for (int mf = 0; mf < 4; ++mf)
#pragma unroll
        for (int h = 0; h < 2; ++h)
            base2[mf * 2 + h] = alpha2 * Xsq[p0 + wm * 64 + mf * 16 + (l >> 2) + 8 * h];

    float mS[8], sS[8];
#pragma unroll
    for (int i = 0; i < 8; ++i) { mS[i] = -1e30f; sS[i] = 0.0f; }

    const int rx  = l & 7;
    const int aco = l >> 4;
    const int bco = (l >> 3) & 1;
    uint32_t arow[4], brow[2];
#pragma unroll
    for (int mf = 0; mf < 4; ++mf)
        arow[mf] = (uint32_t)((wm * 64 + mf * 16 + (l & 15)) * 256);
#pragma unroll
    for (int g2 = 0; g2 < 2; ++g2)
        brow[g2] = (uint32_t)((wn * 32 + g2 * 16 + (l & 7) + ((l >> 4) << 3)) * 256);

    const uint32_t Ab = base + OFF_X;
    float accA[4][4][4], accB[4][4][4];

    cpwait<1>();
    __syncthreads();
    mma_tile(accA, Ab, base + OFF_Y(0), arow, brow, aco, bco, rx);
    __syncthreads();

    for (int t = 0; t < QTILES; t += 2) {
        // phase A
        if (t + 2 < QTILES) {
            const size_t q1 = (size_t)(t + 2) * 128;
#pragma unroll
            for (int it = 0; it < 8; ++it) {
                int u = tid + it * 256;
                int r = u >> 4, c = u & 15;
                cpasync16(base + OFF_Y(0) + r * 256 + swzc(c, r),
                          Yhi + (q1 + r) * CDIM + c * 8);
            }
            if (tid < 128) ysq_s[((t + 2) & 3) * 128 + tid] = alpha2 * Ysq[q1 + tid];
        }
        cpcommit();
        cpwait<1>();
        __syncthreads();
        if (t + 1 < QTILES)
            mma_tile(accB, Ab, base + OFF_Y(1), arow, brow, aco, bco, rx);
        epilogue(accA, ysq_s + (t & 3) * 128, base2, mS, sS, colsm, cpm, cps,
                 beta2, l, wm, wn, tid, t, blockIdx.x);

        // phase B
        if (t + 3 < QTILES) {
            const size_t q1 = (size_t)(t + 3) * 128;
#pragma unroll
            for (int it = 0; it < 8; ++it) {
                int u = tid + it * 256;
                int r = u >> 4, c = u & 15;
                cpasync16(base + OFF_Y(1) + r * 256 + swzc(c, r),
                          Yhi + (q1 + r) * CDIM + c * 8);
            }
            if (tid < 128) ysq_s[((t + 3) & 3) * 128 + tid] = alpha2 * Ysq[q1 + tid];
        }
        cpcommit();
        cpwait<1>();
        __syncthreads();
        if (t + 2 < QTILES)
            mma_tile(accA, Ab, base + OFF_Y(0), arow, brow, aco, bco, rx);
        if (t + 1 < QTILES)
            epilogue(accB, ysq_s + ((t + 1) & 3) * 128, base2, mS, sS, colsm, cpm, cps,
                     beta2, l, wm, wn, tid, t + 1, blockIdx.x);
    }

    // row finalization
    __syncthreads();
    if ((l & 3) == 0) {
#pragma unroll
        for (int ri = 0; ri < 8; ++ri) {
            const int mf = ri >> 1, h = ri & 1;
            int rloc = wm * 64 + mf * 16 + (l >> 2) + 8 * h;
            redm[wn * 128 + rloc] = mS[ri];
            reds[wn * 128 + rloc] = sS[ri];
        }
    }
    __syncthreads();
    if (tid < 128) {
        float m = redm[tid], s = reds[tid];
#pragma unroll
        for (int gq = 1; gq < 4; ++gq) merge_ms(m, s, redm[gq * 128 + tid], reds[gq * 128 + tid]);
        rowm[p0 + tid] = m;
        rows[p0 + tid] = s;
    }
}

// ---------------- reduce1: fused colmerge + partial LSE sums ----------------
// Blocks 0..127: merge col partials for 64 q each, emit per-block sum of col LSEs.
// Blocks 128..159: partial-sum row LSEs (512 rows each).
__global__ void __launch_bounds__(512, 2)
reduce1(const float* __restrict__ cpm, const float* __restrict__ cps,
        const float* __restrict__ rowm, const float* __restrict__ rows,
        float* __restrict__ part1, float* __restrict__ part2) {
    __shared__ float sm_[8][64], ss_[8][64];
    __shared__ float vb[512];
    const int t = threadIdx.x;
    if (blockIdx.x < 128) {
        const int qi = t & 63;
        const int pg = t >> 6;
        const int q  = blockIdx.x * 64 + qi;
        float mv[16], sv[16];
        float M = -1e30f;
#pragma unroll
        for (int i = 0; i < 16; ++i) {
            int p = pg * 16 + i;
            mv[i] = __ldg(cpm + (size_t)p * MCODE + q);
            sv[i] = __ldg(cps + (size_t)p * MCODE + q);
            M = fmaxf(M, mv[i]);
        }
        float S = 0.0f;
#pragma unroll
        for (int i = 0; i < 16; ++i) S += sv[i] * ex2f(mv[i] - M);
        sm_[pg][qi] = M; ss_[pg][qi] = S;
        __syncthreads();
        if (pg == 0) {
            float M2 = M;
#pragma unroll
            for (int g = 1; g < 8; ++g) M2 = fmaxf(M2, sm_[g][qi]);
            float S2 = 0.0f;
#pragma unroll
            for (int g = 0; g < 8; ++g) S2 += ss_[g][qi] * ex2f(sm_[g][qi] - M2);
            vb[qi] = M2 + __log2f(S2);
        }
        __syncthreads();
        // fixed-order tree over 64 values
        if (t < 32) vb[t] = vb[t] + vb[t + 32];
        __syncthreads();
        if (t < 16) vb[t] = vb[t] + vb[t + 16];
        __syncthreads();
        if (t < 8)  vb[t] = vb[t] + vb[t + 8];
        __syncthreads();
        if (t < 4)  vb[t] = vb[t] + vb[t + 4];
        __syncthreads();
        if (t == 0) part2[blockIdx.x] = (vb[0] + vb[1]) + (vb[2] + vb[3]);
    } else {
        const int i = (blockIdx.x - 128) * 512 + t;
        vb[t] = rowm[i] + __log2f(rows[i]);
        __syncthreads();
        for (int st = 256; st; st >>= 1) {
            if (t < st) vb[t] += vb[t + st];
            __syncthreads();
        }
        if (t == 0) part1[blockIdx.x - 128] = vb[0];
    }
}

// ---------------- reduce2: final combine (tiny, deterministic) ----------------
__global__ void reduce2(const float* __restrict__ part1, const float* __restrict__ part2,
                        const float* __restrict__ lsg, float* __restrict__ out) {
    __shared__ float s1[32], s2[128];
    const int t = threadIdx.x;
    if (t < 32)  s1[t] = part1[t];
    if (t < 128) s2[t] = part2[t];
    __syncthreads();
    if (t == 0) {
        float r = 0.0f;
#pragma unroll
        for (int i = 0; i < 32; ++i) r += s1[i];
        float c = 0.0f;
#pragma unroll
        for (int i = 0; i < 128; ++i) c += s2[i];
        float ls  = lsg[0];
        float cst = 0.5f * (float)CDIM * (2.0f * ls - 1.0f);
        double m1 = 0.6931471805599453 * ((double)r / (double)NTOK);
        double m2 = 0.6931471805599453 * ((double)c / (double)MCODE);
        out[0] = (float)(-m1) + cst + logf((float)MCODE);
        out[1] = (float)(-m2) + cst + logf((float)NTOK);
    }
}

// ---------------- launch ----------------
extern "C" void kernel_launch(void* const* d_in, const int* in_sizes, int n_in,
                              void* d_out, int out_size) {
    (void)in_sizes; (void)n_in; (void)out_size;
    const float* z   = (const float*)d_in[0];
    const float* e   = (const float*)d_in[1];
    const float* lsg = (const float*)d_in[2];
    float* out = (float*)d_out;

    float *zsq, *esq, *rm, *rs, *cpm, *cps, *p1, *p2;
    __nv_bfloat16 *zhi, *ehi;
    cudaGetSymbolAddress((void**)&zhi, g_zhi);
    cudaGetSymbolAddress((void**)&ehi, g_ehi);
    cudaGetSymbolAddress((void**)&zsq, g_zsq);
    cudaGetSymbolAddress((void**)&esq, g_esq);
    cudaGetSymbolAddress((void**)&rm,  g_rm);
    cudaGetSymbolAddress((void**)&rs,  g_rs);
    cudaGetSymbolAddress((void**)&cpm, g_cpm);
    cudaGetSymbolAddress((void**)&cps, g_cps);
    cudaGetSymbolAddress((void**)&p1,  g_part1);
    cudaGetSymbolAddress((void**)&p2,  g_part2);

    cudaFuncSetAttribute(lse_single, cudaFuncAttributeMaxDynamicSharedMemorySize, SMEM_BYTES);

    fuse_prep<<<512 + MCODE / 8, 256>>>(z, e, zhi, zsq, ehi, esq);

    lse_single<<<PTILES, 256, SMEM_BYTES>>>(zhi, zsq, ehi, esq, lsg, rm, rs, cpm, cps);

    reduce1<<<160, 512>>>(cpm, cps, rm, rs, p1, p2);
    reduce2<<<1, 128>>>(p1, p2, lsg, out);
}